// round 4
// baseline (speedup 1.0000x reference)
#include <cuda_runtime.h>
#include <cuda_bf16.h>
#include <math.h>
#include <stdint.h>

#define CDIM 320
#define T0   2048
#define NLEV 12
#define NDIV 11.0

// fp32 pyramid levels 1..11 (level 0 = harness input)
__device__ __align__(16) float g_p1[8 * CDIM * 2047];
__device__ __align__(16) float g_p2[8 * CDIM * 2047];
// bf16 pyramid levels 0..11
__device__ __align__(16) __nv_bfloat16 g_b1[8 * CDIM * 4095];
__device__ __align__(16) __nv_bfloat16 g_b2[8 * CDIM * 4095];
// level-0 col-split partial stats: [half][b*4096 + row]
__device__ float g_pm[2][32768];
__device__ float g_ps[2][32768];

__device__ double g_lse_i[NLEV], g_pos_i[NLEV], g_lse_t[NLEV], g_pos_t[NLEV];

__constant__ int c_T[12]      = {2048,1024,512,256,128,64,32,16,8,4,2,1};
__constant__ int c_offb[12]   = {0,5242880,7864320,9175040,9830400,10158080,10321920,10403840,10444800,10465280,10475520,10480640};
__constant__ int c_offf[12]   = {0,0,2621440,3932160,4587520,4915200,5079040,5160960,5201920,5222400,5232640,5237760};
__constant__ int c_tstart[12] = {0,2048,3072,3584,3840,3968,4032,4064,4080,4088,4092,4094};
__constant__ int c_bstart[12] = {0,512,640,704,736,752,760,768,776,784,792,800};

__global__ void init_acc() {
    int i = threadIdx.x;
    if (i < NLEV) {
        g_lse_i[i] = 0.0; g_pos_i[i] = 0.0;
        g_lse_t[i] = 0.0; g_pos_t[i] = 0.0;
    }
}

// ---------------- one-shot pyramid: all pool levels, fp32 + bf16 ----------------
__global__ void pyramid_kernel(const float* __restrict__ z1, const float* __restrict__ z2) {
    __shared__ float s[3072];
    int bc = blockIdx.x;                 // 0..2559 = b*320 + c
    int y  = blockIdx.y;
    const float* src = (y ? z2 : z1) + (size_t)bc * T0;
    float* pf = y ? g_p2 : g_p1;
    __nv_bfloat16* pb = y ? g_b2 : g_b1;
    int tid = threadIdx.x;               // 256

    __nv_bfloat162* pb0 = (__nv_bfloat162*)(pb + (size_t)bc * T0);
    for (int i = tid; i < 512; i += 256) {
        float4 v = ((const float4*)src)[i];
        ((float4*)s)[i] = v;
        __nv_bfloat162 o1, o2;
        o1.x = __float2bfloat16(v.x); o1.y = __float2bfloat16(v.y);
        o2.x = __float2bfloat16(v.z); o2.y = __float2bfloat16(v.w);
        pb0[2 * i]     = o1;
        pb0[2 * i + 1] = o2;
    }
    __syncthreads();

    float* cur = s;
    float* nxt = s + 2048;
    for (int k = 1; k < 12; k++) {
        int Tk = T0 >> k;
        for (int i = tid; i < Tk; i += 256) {
            float v = fmaxf(cur[2 * i], cur[2 * i + 1]);
            nxt[i] = v;
            pf[c_offf[k] + (size_t)bc * Tk + i] = v;
            pb[c_offb[k] + (size_t)bc * Tk + i] = __float2bfloat16(v);
        }
        __syncthreads();
        float* tmp = cur; cur = nxt; nxt = tmp;
    }
}

// ---------------- instance contrast, all levels fused ----------------
__global__ void inst_all(const float* __restrict__ z1, const float* __restrict__ z2) {
    __shared__ float Zs[16][CDIM + 1];
    __shared__ float simS[16][17];
    __shared__ float red[24];
    int bid = blockIdx.x;
    int lvl = 0;
#pragma unroll
    for (int k = 1; k < 12; k++) if (bid >= c_tstart[k]) lvl = k;
    int T = c_T[lvl];
    int t = bid - c_tstart[lvl];
    const float* s1 = lvl ? (g_p1 + c_offf[lvl]) : z1;
    const float* s2 = lvl ? (g_p2 + c_offf[lvl]) : z2;
    int tid = threadIdx.x;

    for (int e = tid; e < 16 * CDIM; e += 256) {
        int n = e / CDIM, c = e - n * CDIM;
        const float* src = (n < 8) ? s1 : s2;
        Zs[n][c] = src[((size_t)(n & 7) * CDIM + c) * T + t];
    }
    __syncthreads();

    int n = tid >> 4, m = tid & 15;
    float acc = 0.f;
#pragma unroll 8
    for (int c = 0; c < CDIM; c++) acc = fmaf(Zs[n][c], Zs[m][c], acc);
    simS[n][m] = acc;
    __syncthreads();

    if (tid < 16) {
        float mx = -INFINITY;
#pragma unroll
        for (int j = 0; j < 16; j++) if (j != tid) mx = fmaxf(mx, simS[tid][j]);
        float s = 0.f;
#pragma unroll
        for (int j = 0; j < 16; j++) if (j != tid) s += __expf(simS[tid][j] - mx);
        red[tid] = mx + logf(s);
    }
    if (tid >= 16 && tid < 24) {
        int i = tid - 16;
        red[tid] = simS[i][8 + i];
    }
    __syncthreads();
    if (tid == 0) {
        float lsum = 0.f, psum = 0.f;
        for (int j = 0; j < 16; j++) lsum += red[j];
        for (int j = 16; j < 24; j++) psum += red[j];
        atomicAdd(&g_lse_i[lvl], (double)lsum);
        atomicAdd(&g_pos_i[lvl], (double)psum);
    }
}

// ---------------- temporal contrast: bf16 HMMA, A-resident, cp.async ----------------

__device__ __forceinline__ uint32_t s2u(const void* p) {
    return (uint32_t)__cvta_generic_to_shared(p);
}
__device__ __forceinline__ void ldsm4t(uint32_t& r0, uint32_t& r1, uint32_t& r2, uint32_t& r3,
                                       uint32_t a) {
    asm volatile("ldmatrix.sync.aligned.m8n8.x4.trans.shared.b16 {%0,%1,%2,%3}, [%4];"
                 : "=r"(r0), "=r"(r1), "=r"(r2), "=r"(r3) : "r"(a));
}
__device__ __forceinline__ void mma16816(float* c, uint32_t a0, uint32_t a1, uint32_t a2,
                                         uint32_t a3, uint32_t b0, uint32_t b1) {
    asm volatile(
        "mma.sync.aligned.m16n8k16.row.col.f32.bf16.bf16.f32 "
        "{%0,%1,%2,%3},{%4,%5,%6,%7},{%8,%9},{%0,%1,%2,%3};"
        : "+f"(c[0]), "+f"(c[1]), "+f"(c[2]), "+f"(c[3])
        : "r"(a0), "r"(a1), "r"(a2), "r"(a3), "r"(b0), "r"(b1));
}
__device__ __forceinline__ void cpa16(uint32_t d, const void* s) {
    asm volatile("cp.async.cg.shared.global [%0], [%1], 16;" :: "r"(d), "l"(s));
}

// warp tile 32 rows x 128 cols; one 32-deep K chunk
__device__ __forceinline__ void consume32(float acc[2][16][4], uint32_t uA, int kbase,
                                          uint32_t baseB, int mw, int li, int sel) {
#pragma unroll
    for (int ks = 0; ks < 32; ks += 16) {
        int rowkA = kbase + ks + ((sel >> 1) << 3) + li;
        uint32_t sw = (uint32_t)((rowkA & 7) << 4);
        uint32_t a[2][4];
#pragma unroll
        for (int rb = 0; rb < 2; rb++) {
            uint32_t abyte = ((uint32_t)(2 * (mw + (rb << 4) + ((sel & 1) << 3)))) ^ sw;
            ldsm4t(a[rb][0], a[rb][1], a[rb][2], a[rb][3], uA + (rowkA << 8) + abyte);
        }
        int rowkB = ks + ((sel & 1) << 3) + li;
        uint32_t swb = (uint32_t)((rowkB & 7) << 4);
        uint32_t nsel = (uint32_t)((sel >> 1) << 4);
        uint32_t rowbB = baseB + (rowkB << 8);
#pragma unroll
        for (int p = 0; p < 8; p++) {
            uint32_t bb = (((uint32_t)(p << 5)) | nsel) ^ swb;
            uint32_t b0, b1, b2, b3;
            ldsm4t(b0, b1, b2, b3, rowbB + bb);
#pragma unroll
            for (int rb = 0; rb < 2; rb++) {
                mma16816(acc[rb][2 * p],     a[rb][0], a[rb][1], a[rb][2], a[rb][3], b0, b1);
                mma16816(acc[rb][2 * p + 1], a[rb][0], a[rb][1], a[rb][2], a[rb][3], b2, b3);
            }
        }
    }
}

#define SM_A_BYTES 81920
#define SM_B_BYTES 8192
#define SM_DYN (SM_A_BYTES + 3 * SM_B_BYTES + 32)

__global__ void __launch_bounds__(128)
temp_all() {
    extern __shared__ __align__(16) unsigned char sm[];
    uint32_t uA = s2u(sm);
    uint32_t uB0 = uA + SM_A_BYTES;
    uint32_t uB1 = uB0 + SM_B_BYTES;
    uint32_t uB2 = uB1 + SM_B_BYTES;
    float* redbuf = (float*)(sm + SM_A_BYTES + 3 * SM_B_BYTES);

    int bid = blockIdx.x;
    int lvl = 0;
#pragma unroll
    for (int k = 1; k < 12; k++) if (bid >= c_bstart[k]) lvl = k;
    int T = c_T[lvl];
    int local = bid - c_bstart[lvl];
    const __nv_bfloat16* zl1 = g_b1 + c_offb[lvl];
    const __nv_bfloat16* zl2 = g_b2 + c_offb[lvl];

    int tid = threadIdx.x, lane = tid & 31, warp = tid >> 5;
    int mw = warp << 5;
    int gid = lane >> 2, tidq = lane & 3;
    int li = lane & 7, sel = lane >> 3;

    float mrun[4] = {-INFINITY, -INFINITY, -INFINITY, -INFINITY};
    float srun[4] = {0.f, 0.f, 0.f, 0.f};
    float pos = 0.f;

    int b, r0, ct0, nct, half = 0;
    bool fast = (T >= 128);
    if (lvl == 0) {
        b = local >> 6;
        int rem = local & 63;
        r0 = (rem >> 1) << 7;
        half = rem & 1;
        ct0 = half << 4;
        nct = 16;
    } else if (fast) {
        int rbc = T >> 6;
        b = local / rbc;
        r0 = (local - b * rbc) << 7;
        ct0 = 0;
        nct = (2 * T) >> 7;
    } else {
        b = local; r0 = 0; ct0 = 0; nct = 1;
    }

    const __nv_bfloat16* z1b = zl1 + (size_t)b * CDIM * T;
    const __nv_bfloat16* z2b = zl2 + (size_t)b * CDIM * T;
    int M = 2 * T;

    if (fast) {
        const char* srcA = (const char*)((r0 < T) ? z1b : z2b);
        int rA0 = (r0 < T) ? r0 : r0 - T;
        // load full A tile [K=320][128 rows] once
#pragma unroll 4
        for (int i = tid; i < 5120; i += 128) {
            int k = i >> 4, c = i & 15;
            uint32_t dst = uA + (k << 8) + (((uint32_t)(c << 4)) ^ (uint32_t)((k & 7) << 4));
            cpa16(dst, srcA + ((size_t)k * T + rA0) * 2 + (c << 4));
        }
        asm volatile("cp.async.commit_group;" ::: "memory");

        for (int ci = 0; ci < nct; ci++) {
            int c0 = (ct0 + ci) << 7;
            const char* srcB = (const char*)((c0 < T) ? z1b : z2b);
            int cB0 = (c0 < T) ? c0 : c0 - T;

            // prefetch chunks 0 and 1
#pragma unroll
            for (int pc = 0; pc < 2; pc++) {
                uint32_t bu = pc ? uB1 : uB0;
#pragma unroll
                for (int i = tid; i < 512; i += 128) {
                    int k = i >> 4, c = i & 15;
                    uint32_t dst = bu + (k << 8) + (((uint32_t)(c << 4)) ^ (uint32_t)((k & 7) << 4));
                    cpa16(dst, srcB + ((size_t)(pc * 32 + k) * T + cB0) * 2 + (c << 4));
                }
                asm volatile("cp.async.commit_group;" ::: "memory");
            }

            float acc[2][16][4];
#pragma unroll
            for (int q = 0; q < 2; q++)
#pragma unroll
                for (int nt = 0; nt < 16; nt++)
#pragma unroll
                    for (int j = 0; j < 4; j++) acc[q][nt][j] = 0.f;

#pragma unroll 1
            for (int kc = 0; kc < 10; kc++) {
                if (kc < 9) asm volatile("cp.async.wait_group 1;" ::: "memory");
                else        asm volatile("cp.async.wait_group 0;" ::: "memory");
                __syncthreads();
                int r = kc % 3;
                uint32_t bu = (r == 0) ? uB0 : (r == 1) ? uB1 : uB2;
                consume32(acc, uA, kc * 32, bu, mw, li, sel);
                if (kc < 8) {
                    int tc = kc + 2;
                    int r2 = tc % 3;
                    uint32_t pu = (r2 == 0) ? uB0 : (r2 == 1) ? uB1 : uB2;
#pragma unroll
                    for (int i = tid; i < 512; i += 128) {
                        int k = i >> 4, c = i & 15;
                        uint32_t dst = pu + (k << 8) + (((uint32_t)(c << 4)) ^ (uint32_t)((k & 7) << 4));
                        cpa16(dst, srcB + ((size_t)(tc * 32 + k) * T + cB0) * 2 + (c << 4));
                    }
                    asm volatile("cp.async.commit_group;" ::: "memory");
                }
            }

            // online-LSE epilogue for this 128-col tile
            bool diag = (c0 == r0);
            bool isP  = (c0 == r0 + T);
#pragma unroll
            for (int rb = 0; rb < 2; rb++)
#pragma unroll
            for (int h = 0; h < 2; h++) {
                int e = 2 * rb + h;
                int lr = mw + (rb << 4) + (h << 3) + gid;
                float tm = -INFINITY;
#pragma unroll
                for (int nt = 0; nt < 16; nt++)
#pragma unroll
                for (int j = 0; j < 2; j++) {
                    int lc = (nt << 3) + (tidq << 1) + j;
                    float v = acc[rb][nt][(h << 1) + j];
                    if (isP && lc == lr) pos += v;
                    if (diag && lc == lr) v = -INFINITY;
                    acc[rb][nt][(h << 1) + j] = v;
                    tm = fmaxf(tm, v);
                }
                tm = fmaxf(tm, __shfl_xor_sync(0xffffffffu, tm, 1));
                tm = fmaxf(tm, __shfl_xor_sync(0xffffffffu, tm, 2));
                float nm = fmaxf(mrun[e], tm);
                float s = 0.f;
#pragma unroll
                for (int nt = 0; nt < 16; nt++)
#pragma unroll
                for (int j = 0; j < 2; j++)
                    s += __expf(acc[rb][nt][(h << 1) + j] - nm);
                s += __shfl_xor_sync(0xffffffffu, s, 1);
                s += __shfl_xor_sync(0xffffffffu, s, 2);
                float sc = (mrun[e] == -INFINITY) ? 0.f : __expf(mrun[e] - nm);
                srun[e] = srun[e] * sc + s;
                mrun[e] = nm;
            }
            __syncthreads();
        }
    } else {
        // ---- slow path: M = 2T <= 128, single padded tile, B == A ----
#pragma unroll 1
        for (int i = tid; i < 320 * 128; i += 128) {
            int k = i >> 7, m = i & 127;
            unsigned short v = 0;
            if (m < T)      v = *(const unsigned short*)(z1b + (size_t)k * T + m);
            else if (m < M) v = *(const unsigned short*)(z2b + (size_t)k * T + (m - T));
            *(unsigned short*)(sm + (k << 8) + (((uint32_t)(m << 1)) ^ (uint32_t)((k & 7) << 4))) = v;
        }
        __syncthreads();

        float acc[2][16][4];
#pragma unroll
        for (int q = 0; q < 2; q++)
#pragma unroll
            for (int nt = 0; nt < 16; nt++)
#pragma unroll
                for (int j = 0; j < 4; j++) acc[q][nt][j] = 0.f;

#pragma unroll 1
        for (int kc = 0; kc < 10; kc++)
            consume32(acc, uA, kc * 32, uA + (uint32_t)((kc * 32) << 8), mw, li, sel);

#pragma unroll
        for (int rb = 0; rb < 2; rb++)
#pragma unroll
        for (int h = 0; h < 2; h++) {
            int e = 2 * rb + h;
            int lr = mw + (rb << 4) + (h << 3) + gid;
            float tm = -INFINITY;
#pragma unroll
            for (int nt = 0; nt < 16; nt++)
#pragma unroll
            for (int j = 0; j < 2; j++) {
                int lc = (nt << 3) + (tidq << 1) + j;
                float v = acc[rb][nt][(h << 1) + j];
                if (lr < T && lc == lr + T) pos += v;
                if (lc >= M || lc == lr) v = -INFINITY;
                acc[rb][nt][(h << 1) + j] = v;
                tm = fmaxf(tm, v);
            }
            tm = fmaxf(tm, __shfl_xor_sync(0xffffffffu, tm, 1));
            tm = fmaxf(tm, __shfl_xor_sync(0xffffffffu, tm, 2));
            float s = 0.f;
            if (tm > -INFINITY) {
#pragma unroll
                for (int nt = 0; nt < 16; nt++)
#pragma unroll
                for (int j = 0; j < 2; j++)
                    s += __expf(acc[rb][nt][(h << 1) + j] - tm);
            }
            s += __shfl_xor_sync(0xffffffffu, s, 1);
            s += __shfl_xor_sync(0xffffffffu, s, 2);
            srun[e] = s;
            mrun[e] = tm;
        }
    }

    // ---- output ----
    if (lvl == 0) {
        if (tidq == 0) {
#pragma unroll
            for (int e = 0; e < 4; e++) {
                int lr = mw + ((e >> 1) << 4) + ((e & 1) << 3) + gid;
                int idx = (b << 12) + r0 + lr;
                g_pm[half][idx] = mrun[e];
                g_ps[half][idx] = srun[e];
            }
        }
        float ps = pos;
#pragma unroll
        for (int o = 16; o; o >>= 1) ps += __shfl_xor_sync(0xffffffffu, ps, o);
        if (lane == 0) redbuf[warp] = ps;
        __syncthreads();
        if (tid == 0) {
            float p2 = redbuf[0] + redbuf[1] + redbuf[2] + redbuf[3];
            atomicAdd(&g_pos_t[0], (double)p2);
        }
    } else {
        float lsum = 0.f;
        if (tidq == 0) {
#pragma unroll
            for (int e = 0; e < 4; e++) {
                int lr = mw + ((e >> 1) << 4) + ((e & 1) << 3) + gid;
                int row = r0 + lr;
                if (row < M && srun[e] > 0.f) lsum += mrun[e] + logf(srun[e]);
            }
        }
        float ps = pos;
#pragma unroll
        for (int o = 16; o; o >>= 1) {
            lsum += __shfl_xor_sync(0xffffffffu, lsum, o);
            ps   += __shfl_xor_sync(0xffffffffu, ps, o);
        }
        if (lane == 0) { redbuf[warp] = lsum; redbuf[4 + warp] = ps; }
        __syncthreads();
        if (tid == 0) {
            float a = redbuf[0] + redbuf[1] + redbuf[2] + redbuf[3];
            float p2 = redbuf[4] + redbuf[5] + redbuf[6] + redbuf[7];
            atomicAdd(&g_lse_t[lvl], (double)a);
            atomicAdd(&g_pos_t[lvl], (double)p2);
        }
    }
}

// merge the two level-0 col-halves per row, sum LSE into g_lse_t[0]
__global__ void lsered_kernel() {
    __shared__ float rb[8];
    int i = blockIdx.x * 256 + threadIdx.x;   // 32768 rows
    float m0 = g_pm[0][i], m1 = g_pm[1][i];
    float s0 = g_ps[0][i], s1 = g_ps[1][i];
    float m = fmaxf(m0, m1);
    float v = m + logf(s0 * __expf(m0 - m) + s1 * __expf(m1 - m));
#pragma unroll
    for (int o = 16; o; o >>= 1) v += __shfl_xor_sync(0xffffffffu, v, o);
    if ((threadIdx.x & 31) == 0) rb[threadIdx.x >> 5] = v;
    __syncthreads();
    if (threadIdx.x == 0) {
        float s = 0.f;
        for (int w = 0; w < 8; w++) s += rb[w];
        atomicAdd(&g_lse_t[0], (double)s);
    }
}

__global__ void finalize_kernel(float* out) {
    double inst = 0.0, temp = 0.0;
    for (int k = 0; k < NLEV; k++) {
        double Tk = (double)(T0 >> k);
        inst += g_lse_i[k] / (16.0 * Tk) - g_pos_i[k] / (8.0 * Tk);
        temp += g_lse_t[k] / (16.0 * Tk) - g_pos_t[k] / (8.0 * Tk);
    }
    inst /= NDIV;
    temp /= NDIV;
    out[0] = (float)(0.5 * (inst + temp));
    out[1] = (float)inst;
    out[2] = (float)temp;
}

extern "C" void kernel_launch(void* const* d_in, const int* in_sizes, int n_in,
                              void* d_out, int out_size) {
    const float* z1 = (const float*)d_in[0];
    const float* z2 = (const float*)d_in[1];
    float* out = (float*)d_out;

    cudaFuncSetAttribute(temp_all, cudaFuncAttributeMaxDynamicSharedMemorySize, SM_DYN);

    init_acc<<<1, 32>>>();
    dim3 pg(2560, 2);
    pyramid_kernel<<<pg, 256>>>(z1, z2);
    inst_all<<<4095, 256>>>(z1, z2);
    temp_all<<<808, 128, SM_DYN>>>();
    lsered_kernel<<<128, 256>>>();
    finalize_kernel<<<1, 1>>>(out);
}

// round 5
// speedup vs baseline: 1.1248x; 1.1248x over previous
#include <cuda_runtime.h>
#include <cuda_bf16.h>
#include <math.h>
#include <stdint.h>

#define CDIM 320
#define T0   2048
#define NLEV 12
#define NDIV 11.0

// fp32 pyramid levels 1..11 (level 0 = harness input)
__device__ __align__(16) float g_p1[8 * CDIM * 2047];
__device__ __align__(16) float g_p2[8 * CDIM * 2047];
// bf16 pyramid levels 0..11
__device__ __align__(16) __nv_bfloat16 g_b1[8 * CDIM * 4095];
__device__ __align__(16) __nv_bfloat16 g_b2[8 * CDIM * 4095];
// level-0 col-split partial stats: [half][b*4096 + row]
__device__ float g_pm[2][32768];
__device__ float g_ps[2][32768];

__device__ double g_lse_i[NLEV], g_pos_i[NLEV], g_lse_t[NLEV], g_pos_t[NLEV];

__constant__ int c_T[12]      = {2048,1024,512,256,128,64,32,16,8,4,2,1};
__constant__ int c_offb[12]   = {0,5242880,7864320,9175040,9830400,10158080,10321920,10403840,10444800,10465280,10475520,10480640};
__constant__ int c_offf[12]   = {0,0,2621440,3932160,4587520,4915200,5079040,5160960,5201920,5222400,5232640,5237760};
__constant__ int c_tstart[12] = {0,2048,3072,3584,3840,3968,4032,4064,4080,4088,4092,4094};
__constant__ int c_bstart[12] = {0,512,640,704,736,752,760,768,776,784,792,800};

__global__ void init_acc() {
    int i = threadIdx.x;
    if (i < NLEV) {
        g_lse_i[i] = 0.0; g_pos_i[i] = 0.0;
        g_lse_t[i] = 0.0; g_pos_t[i] = 0.0;
    }
}

// ---------------- one-shot pyramid: all pool levels, fp32 + bf16 ----------------
__global__ void pyramid_kernel(const float* __restrict__ z1, const float* __restrict__ z2) {
    __shared__ float s[3072];
    int bc = blockIdx.x;                 // 0..2559 = b*320 + c
    int y  = blockIdx.y;
    const float* src = (y ? z2 : z1) + (size_t)bc * T0;
    float* pf = y ? g_p2 : g_p1;
    __nv_bfloat16* pb = y ? g_b2 : g_b1;
    int tid = threadIdx.x;               // 256

    __nv_bfloat162* pb0 = (__nv_bfloat162*)(pb + (size_t)bc * T0);
    for (int i = tid; i < 512; i += 256) {
        float4 v = ((const float4*)src)[i];
        ((float4*)s)[i] = v;
        __nv_bfloat162 o1, o2;
        o1.x = __float2bfloat16(v.x); o1.y = __float2bfloat16(v.y);
        o2.x = __float2bfloat16(v.z); o2.y = __float2bfloat16(v.w);
        pb0[2 * i]     = o1;
        pb0[2 * i + 1] = o2;
    }
    __syncthreads();

    float* cur = s;
    float* nxt = s + 2048;
    for (int k = 1; k < 12; k++) {
        int Tk = T0 >> k;
        for (int i = tid; i < Tk; i += 256) {
            float v = fmaxf(cur[2 * i], cur[2 * i + 1]);
            nxt[i] = v;
            pf[c_offf[k] + (size_t)bc * Tk + i] = v;
            pb[c_offb[k] + (size_t)bc * Tk + i] = __float2bfloat16(v);
        }
        __syncthreads();
        float* tmp = cur; cur = nxt; nxt = tmp;
    }
}

// ---------------- instance contrast, all levels fused ----------------
__global__ void inst_all(const float* __restrict__ z1, const float* __restrict__ z2) {
    __shared__ float Zs[16][CDIM + 1];
    __shared__ float simS[16][17];
    __shared__ float red[24];
    int bid = blockIdx.x;
    int lvl = 0;
#pragma unroll
    for (int k = 1; k < 12; k++) if (bid >= c_tstart[k]) lvl = k;
    int T = c_T[lvl];
    int t = bid - c_tstart[lvl];
    const float* s1 = lvl ? (g_p1 + c_offf[lvl]) : z1;
    const float* s2 = lvl ? (g_p2 + c_offf[lvl]) : z2;
    int tid = threadIdx.x;

    for (int e = tid; e < 16 * CDIM; e += 256) {
        int n = e / CDIM, c = e - n * CDIM;
        const float* src = (n < 8) ? s1 : s2;
        Zs[n][c] = src[((size_t)(n & 7) * CDIM + c) * T + t];
    }
    __syncthreads();

    int n = tid >> 4, m = tid & 15;
    float acc = 0.f;
#pragma unroll 8
    for (int c = 0; c < CDIM; c++) acc = fmaf(Zs[n][c], Zs[m][c], acc);
    simS[n][m] = acc;
    __syncthreads();

    if (tid < 16) {
        float mx = -INFINITY;
#pragma unroll
        for (int j = 0; j < 16; j++) if (j != tid) mx = fmaxf(mx, simS[tid][j]);
        float s = 0.f;
#pragma unroll
        for (int j = 0; j < 16; j++) if (j != tid) s += __expf(simS[tid][j] - mx);
        red[tid] = mx + logf(s);
    }
    if (tid >= 16 && tid < 24) {
        int i = tid - 16;
        red[tid] = simS[i][8 + i];
    }
    __syncthreads();
    if (tid == 0) {
        float lsum = 0.f, psum = 0.f;
        for (int j = 0; j < 16; j++) lsum += red[j];
        for (int j = 16; j < 24; j++) psum += red[j];
        atomicAdd(&g_lse_i[lvl], (double)lsum);
        atomicAdd(&g_pos_i[lvl], (double)psum);
    }
}

// ---------------- temporal contrast: bf16 HMMA ----------------

__device__ __forceinline__ uint32_t s2u(const void* p) {
    return (uint32_t)__cvta_generic_to_shared(p);
}
__device__ __forceinline__ void ldsm4t(uint32_t& r0, uint32_t& r1, uint32_t& r2, uint32_t& r3,
                                       uint32_t a) {
    asm volatile("ldmatrix.sync.aligned.m8n8.x4.trans.shared.b16 {%0,%1,%2,%3}, [%4];"
                 : "=r"(r0), "=r"(r1), "=r"(r2), "=r"(r3) : "r"(a));
}
__device__ __forceinline__ void mma16816(float* c, uint32_t a0, uint32_t a1, uint32_t a2,
                                         uint32_t a3, uint32_t b0, uint32_t b1) {
    asm volatile(
        "mma.sync.aligned.m16n8k16.row.col.f32.bf16.bf16.f32 "
        "{%0,%1,%2,%3},{%4,%5,%6,%7},{%8,%9},{%0,%1,%2,%3};"
        : "+f"(c[0]), "+f"(c[1]), "+f"(c[2]), "+f"(c[3])
        : "r"(a0), "r"(a1), "r"(a2), "r"(a3), "r"(b0), "r"(b1));
}
__device__ __forceinline__ void cpa16(uint32_t d, const void* s) {
    asm volatile("cp.async.cg.shared.global [%0], [%1], 16;" :: "r"(d), "l"(s));
}

// warp tile 32 rows x 64 cols; one 32-deep K chunk.
// chb = (col half)*128 bytes within the 256B B row.
__device__ __forceinline__ void consume32(float acc[2][8][4], uint32_t uA, int kbase,
                                          uint32_t baseB, int mw, int chb, int li, int sel) {
#pragma unroll
    for (int ks = 0; ks < 32; ks += 16) {
        int rowkA = kbase + ks + ((sel >> 1) << 3) + li;
        uint32_t sw = (uint32_t)((rowkA & 7) << 4);
        uint32_t a[2][4];
#pragma unroll
        for (int rb = 0; rb < 2; rb++) {
            uint32_t abyte = ((uint32_t)(2 * (mw + (rb << 4) + ((sel & 1) << 3)))) ^ sw;
            ldsm4t(a[rb][0], a[rb][1], a[rb][2], a[rb][3], uA + (rowkA << 8) + abyte);
        }
        int rowkB = ks + ((sel & 1) << 3) + li;
        uint32_t swb = (uint32_t)((rowkB & 7) << 4);
        uint32_t nsel = (uint32_t)((sel >> 1) << 4);
        uint32_t rowbB = baseB + (rowkB << 8);
#pragma unroll
        for (int p = 0; p < 4; p++) {
            uint32_t bb = ((uint32_t)(chb + (p << 5)) | nsel) ^ swb;
            uint32_t b0, b1, b2, b3;
            ldsm4t(b0, b1, b2, b3, rowbB + bb);
#pragma unroll
            for (int rb = 0; rb < 2; rb++) {
                mma16816(acc[rb][2 * p],     a[rb][0], a[rb][1], a[rb][2], a[rb][3], b0, b1);
                mma16816(acc[rb][2 * p + 1], a[rb][0], a[rb][1], a[rb][2], a[rb][3], b2, b3);
            }
        }
    }
}

#define SM_A_BYTES 81920
#define SM_B_BYTES 8192
#define SM_RED     1152
#define SM_DYN (SM_A_BYTES + 3 * SM_B_BYTES + SM_RED)

__global__ void __launch_bounds__(256)
temp_all() {
    extern __shared__ __align__(16) unsigned char sm[];
    uint32_t uA = s2u(sm);
    uint32_t uB0 = uA + SM_A_BYTES;
    uint32_t uB1 = uB0 + SM_B_BYTES;
    uint32_t uB2 = uB1 + SM_B_BYTES;
    float* mrg = (float*)(sm + SM_A_BYTES + 3 * SM_B_BYTES); // [0..127]=m, [128..255]=s
    float* redbuf = mrg + 256;                               // 16 floats

    int bid = blockIdx.x;
    int lvl = 0;
#pragma unroll
    for (int k = 1; k < 12; k++) if (bid >= c_bstart[k]) lvl = k;
    int T = c_T[lvl];
    int local = bid - c_bstart[lvl];
    const __nv_bfloat16* zl1 = g_b1 + c_offb[lvl];
    const __nv_bfloat16* zl2 = g_b2 + c_offb[lvl];

    int tid = threadIdx.x, lane = tid & 31, warp = tid >> 5;
    int rg = warp & 3, ch = warp >> 2;
    int mw = rg << 5;
    int chb = ch << 7;        // byte offset of col half
    int chc = ch << 6;        // col offset of col half
    int gid = lane >> 2, tidq = lane & 3;
    int li = lane & 7, sel = lane >> 3;

    float mrun[4] = {-INFINITY, -INFINITY, -INFINITY, -INFINITY};
    float srun[4] = {0.f, 0.f, 0.f, 0.f};
    float pos = 0.f;

    int b, r0, ct0, nct, half = 0;
    bool fast = (T >= 128);
    if (lvl == 0) {
        b = local >> 6;
        int rem = local & 63;
        r0 = (rem >> 1) << 7;
        half = rem & 1;
        ct0 = half << 4;
        nct = 16;
    } else if (fast) {
        int rbc = T >> 6;
        b = local / rbc;
        r0 = (local - b * rbc) << 7;
        ct0 = 0;
        nct = (2 * T) >> 7;
    } else {
        b = local; r0 = 0; ct0 = 0; nct = 1;
    }

    const __nv_bfloat16* z1b = zl1 + (size_t)b * CDIM * T;
    const __nv_bfloat16* z2b = zl2 + (size_t)b * CDIM * T;
    int M = 2 * T;

    if (fast) {
        const char* srcA = (const char*)((r0 < T) ? z1b : z2b);
        int rA0 = (r0 < T) ? r0 : r0 - T;
        // load full A tile [K=320][128 rows] once
#pragma unroll 4
        for (int i = tid; i < 5120; i += 256) {
            int k = i >> 4, c = i & 15;
            uint32_t dst = uA + (k << 8) + (((uint32_t)(c << 4)) ^ (uint32_t)((k & 7) << 4));
            cpa16(dst, srcA + ((size_t)k * T + rA0) * 2 + (c << 4));
        }
        asm volatile("cp.async.commit_group;" ::: "memory");

        for (int ci = 0; ci < nct; ci++) {
            int c0 = (ct0 + ci) << 7;
            const char* srcB = (const char*)((c0 < T) ? z1b : z2b);
            int cB0 = (c0 < T) ? c0 : c0 - T;

            // prefetch chunks 0 and 1
#pragma unroll
            for (int pc = 0; pc < 2; pc++) {
                uint32_t bu = pc ? uB1 : uB0;
#pragma unroll
                for (int i = tid; i < 512; i += 256) {
                    int k = i >> 4, c = i & 15;
                    uint32_t dst = bu + (k << 8) + (((uint32_t)(c << 4)) ^ (uint32_t)((k & 7) << 4));
                    cpa16(dst, srcB + ((size_t)(pc * 32 + k) * T + cB0) * 2 + (c << 4));
                }
                asm volatile("cp.async.commit_group;" ::: "memory");
            }

            float acc[2][8][4];
#pragma unroll
            for (int q = 0; q < 2; q++)
#pragma unroll
                for (int nt = 0; nt < 8; nt++)
#pragma unroll
                    for (int j = 0; j < 4; j++) acc[q][nt][j] = 0.f;

#pragma unroll 1
            for (int kc = 0; kc < 10; kc++) {
                if (kc < 9) asm volatile("cp.async.wait_group 1;" ::: "memory");
                else        asm volatile("cp.async.wait_group 0;" ::: "memory");
                __syncthreads();
                int r = kc % 3;
                uint32_t bu = (r == 0) ? uB0 : (r == 1) ? uB1 : uB2;
                consume32(acc, uA, kc * 32, bu, mw, chb, li, sel);
                if (kc < 8) {
                    int tc = kc + 2;
                    int r2 = tc % 3;
                    uint32_t pu = (r2 == 0) ? uB0 : (r2 == 1) ? uB1 : uB2;
#pragma unroll
                    for (int i = tid; i < 512; i += 256) {
                        int k = i >> 4, c = i & 15;
                        uint32_t dst = pu + (k << 8) + (((uint32_t)(c << 4)) ^ (uint32_t)((k & 7) << 4));
                        cpa16(dst, srcB + ((size_t)(tc * 32 + k) * T + cB0) * 2 + (c << 4));
                    }
                    asm volatile("cp.async.commit_group;" ::: "memory");
                }
            }

            // online-LSE epilogue for this 128-col tile (per warp: its 64-col half)
            bool diag = (c0 == r0);
            bool isP  = (c0 == r0 + T);
#pragma unroll
            for (int rb = 0; rb < 2; rb++)
#pragma unroll
            for (int h = 0; h < 2; h++) {
                int e = 2 * rb + h;
                int lr = mw + (rb << 4) + (h << 3) + gid;
                float tm = -INFINITY;
#pragma unroll
                for (int nt = 0; nt < 8; nt++)
#pragma unroll
                for (int j = 0; j < 2; j++) {
                    int lc = chc + (nt << 3) + (tidq << 1) + j;
                    float v = acc[rb][nt][(h << 1) + j];
                    if (isP && lc == lr) pos += v;
                    if (diag && lc == lr) v = -INFINITY;
                    acc[rb][nt][(h << 1) + j] = v;
                    tm = fmaxf(tm, v);
                }
                tm = fmaxf(tm, __shfl_xor_sync(0xffffffffu, tm, 1));
                tm = fmaxf(tm, __shfl_xor_sync(0xffffffffu, tm, 2));
                float nm = fmaxf(mrun[e], tm);
                float s = 0.f;
#pragma unroll
                for (int nt = 0; nt < 8; nt++)
#pragma unroll
                for (int j = 0; j < 2; j++)
                    s += __expf(acc[rb][nt][(h << 1) + j] - nm);
                s += __shfl_xor_sync(0xffffffffu, s, 1);
                s += __shfl_xor_sync(0xffffffffu, s, 2);
                float sc = (mrun[e] == -INFINITY) ? 0.f : __expf(mrun[e] - nm);
                srun[e] = srun[e] * sc + s;
                mrun[e] = nm;
            }
            __syncthreads();
        }
    } else {
        // ---- slow path: M = 2T <= 128, single padded tile, B == A ----
#pragma unroll 1
        for (int i = tid; i < 320 * 128; i += 256) {
            int k = i >> 7, m = i & 127;
            unsigned short v = 0;
            if (m < T)      v = *(const unsigned short*)(z1b + (size_t)k * T + m);
            else if (m < M) v = *(const unsigned short*)(z2b + (size_t)k * T + (m - T));
            *(unsigned short*)(sm + (k << 8) + (((uint32_t)(m << 1)) ^ (uint32_t)((k & 7) << 4))) = v;
        }
        __syncthreads();

        float acc[2][8][4];
#pragma unroll
        for (int q = 0; q < 2; q++)
#pragma unroll
            for (int nt = 0; nt < 8; nt++)
#pragma unroll
                for (int j = 0; j < 4; j++) acc[q][nt][j] = 0.f;

#pragma unroll 1
        for (int kc = 0; kc < 10; kc++)
            consume32(acc, uA, kc * 32, uA + (uint32_t)((kc * 32) << 8), mw, chb, li, sel);

#pragma unroll
        for (int rb = 0; rb < 2; rb++)
#pragma unroll
        for (int h = 0; h < 2; h++) {
            int e = 2 * rb + h;
            int lr = mw + (rb << 4) + (h << 3) + gid;
            float tm = -INFINITY;
#pragma unroll
            for (int nt = 0; nt < 8; nt++)
#pragma unroll
            for (int j = 0; j < 2; j++) {
                int lc = chc + (nt << 3) + (tidq << 1) + j;
                float v = acc[rb][nt][(h << 1) + j];
                if (lr < T && lc == lr + T) pos += v;
                if (lc >= M || lc == lr) v = -INFINITY;
                acc[rb][nt][(h << 1) + j] = v;
                tm = fmaxf(tm, v);
            }
            tm = fmaxf(tm, __shfl_xor_sync(0xffffffffu, tm, 1));
            tm = fmaxf(tm, __shfl_xor_sync(0xffffffffu, tm, 2));
            float s = 0.f;
            if (tm > -INFINITY) {
#pragma unroll
                for (int nt = 0; nt < 8; nt++)
#pragma unroll
                for (int j = 0; j < 2; j++)
                    s += __expf(acc[rb][nt][(h << 1) + j] - tm);
            }
            s += __shfl_xor_sync(0xffffffffu, s, 1);
            s += __shfl_xor_sync(0xffffffffu, s, 2);
            srun[e] = s;
            mrun[e] = tm;
        }
    }

    // ---- merge col-half partials across warp pairs (ch=1 -> ch=0) ----
    if (ch == 1 && tidq == 0) {
#pragma unroll
        for (int e = 0; e < 4; e++) {
            int lr = mw + ((e >> 1) << 4) + ((e & 1) << 3) + gid;
            mrg[lr] = mrun[e];
            mrg[128 + lr] = srun[e];
        }
    }
    __syncthreads();
    if (ch == 0 && tidq == 0) {
#pragma unroll
        for (int e = 0; e < 4; e++) {
            int lr = mw + ((e >> 1) << 4) + ((e & 1) << 3) + gid;
            float m1 = mrg[lr], s1 = mrg[128 + lr];
            float m0 = mrun[e], s0 = srun[e];
            float m = fmaxf(m0, m1);
            float s = 0.f;
            if (m0 > -INFINITY) s += s0 * __expf(m0 - m);
            if (m1 > -INFINITY) s += s1 * __expf(m1 - m);
            mrun[e] = m; srun[e] = s;
        }
    }

    // ---- output ----
    if (lvl == 0) {
        if (ch == 0 && tidq == 0) {
#pragma unroll
            for (int e = 0; e < 4; e++) {
                int lr = mw + ((e >> 1) << 4) + ((e & 1) << 3) + gid;
                int idx = (b << 12) + r0 + lr;
                g_pm[half][idx] = mrun[e];
                g_ps[half][idx] = srun[e];
            }
        }
        float ps = pos;
#pragma unroll
        for (int o = 16; o; o >>= 1) ps += __shfl_xor_sync(0xffffffffu, ps, o);
        if (lane == 0) redbuf[warp] = ps;
        __syncthreads();
        if (tid == 0) {
            float p2 = 0.f;
            for (int w = 0; w < 8; w++) p2 += redbuf[w];
            atomicAdd(&g_pos_t[0], (double)p2);
        }
    } else {
        float lsum = 0.f;
        if (ch == 0 && tidq == 0) {
#pragma unroll
            for (int e = 0; e < 4; e++) {
                int lr = mw + ((e >> 1) << 4) + ((e & 1) << 3) + gid;
                int row = r0 + lr;
                if (row < M && srun[e] > 0.f) lsum += mrun[e] + logf(srun[e]);
            }
        }
        float ps = pos;
#pragma unroll
        for (int o = 16; o; o >>= 1) {
            lsum += __shfl_xor_sync(0xffffffffu, lsum, o);
            ps   += __shfl_xor_sync(0xffffffffu, ps, o);
        }
        if (lane == 0) { redbuf[warp] = lsum; redbuf[8 + warp] = ps; }
        __syncthreads();
        if (tid == 0) {
            float a = 0.f, p2 = 0.f;
            for (int w = 0; w < 8; w++) { a += redbuf[w]; p2 += redbuf[8 + w]; }
            atomicAdd(&g_lse_t[lvl], (double)a);
            atomicAdd(&g_pos_t[lvl], (double)p2);
        }
    }
}

// merge level-0 halves + final combine, single block
__global__ void finalize_kernel(float* out) {
    __shared__ double sred[32];
    int tid = threadIdx.x;
    double acc = 0.0;
    for (int i = tid; i < 32768; i += 1024) {
        float m0 = g_pm[0][i], m1 = g_pm[1][i];
        float s0 = g_ps[0][i], s1 = g_ps[1][i];
        float m = fmaxf(m0, m1);
        acc += (double)(m + logf(s0 * __expf(m0 - m) + s1 * __expf(m1 - m)));
    }
#pragma unroll
    for (int o = 16; o; o >>= 1) acc += __shfl_xor_sync(0xffffffffu, acc, o);
    if ((tid & 31) == 0) sred[tid >> 5] = acc;
    __syncthreads();
    if (tid == 0) {
        double lse0 = 0.0;
        for (int w = 0; w < 32; w++) lse0 += sred[w];
        double inst = 0.0, temp = 0.0;
        for (int k = 0; k < NLEV; k++) {
            double Tk = (double)(T0 >> k);
            double lt = (k == 0) ? lse0 : g_lse_t[k];
            inst += g_lse_i[k] / (16.0 * Tk) - g_pos_i[k] / (8.0 * Tk);
            temp += lt / (16.0 * Tk) - g_pos_t[k] / (8.0 * Tk);
        }
        inst /= NDIV;
        temp /= NDIV;
        out[0] = (float)(0.5 * (inst + temp));
        out[1] = (float)inst;
        out[2] = (float)temp;
    }
}

extern "C" void kernel_launch(void* const* d_in, const int* in_sizes, int n_in,
                              void* d_out, int out_size) {
    const float* z1 = (const float*)d_in[0];
    const float* z2 = (const float*)d_in[1];
    float* out = (float*)d_out;

    cudaFuncSetAttribute(temp_all, cudaFuncAttributeMaxDynamicSharedMemorySize, SM_DYN);

    init_acc<<<1, 32>>>();
    dim3 pg(2560, 2);
    pyramid_kernel<<<pg, 256>>>(z1, z2);
    temp_all<<<808, 256, SM_DYN>>>();
    inst_all<<<4095, 256>>>(z1, z2);
    finalize_kernel<<<1, 1024>>>(out);
}